// round 4
// baseline (speedup 1.0000x reference)
#include <cuda_runtime.h>
#include <math.h>

#define BSZ    16
#define KNEG   65536
#define KP1    65537u
#define NDIM   128
#define NDATA  1000000
#define INV_T  (1.0f / 0.07f)
#define EMA_M  0.5f
#define CAP    16

#define LOGITS       (BSZ * 65537)                  // 1,048,592
#define OUT_LZ_OFF   ((size_t)LOGITS)
#define OUT_MEM_OFF  ((size_t)2 * LOGITS)
#define N4_SCALE     ((size_t)2 * LOGITS / 4)       // 524,296 float4 (exact)
#define NPART        256

#define BUILD_BLKS   ((LOGITS + 255) / 256)         // 4096.06 -> 4097
#define ROW_BLKS     (NDATA / 8)                    // 125,000 (warp per row)
#define FIN_BLKS     ((unsigned)((N4_SCALE + 255) / 256))   // 2049

__device__ unsigned g_cnt[NDATA];          // per-row entry count  (4 MB)
__device__ unsigned g_ent[(size_t)NDATA * CAP];   // packed (b<<17|k) (64 MB)
__device__ double   g_part[NPART];         // hashed partial sums of lx
__device__ unsigned g_done;                // k_finish arrival counter

// ---------------------------------------------------------------------------
// Pass A: invert the gather. One thread per logit appends (b,k) to its
// memory-row bucket. Overflow (never for this input) handled serially here.
// ---------------------------------------------------------------------------
__global__ void __launch_bounds__(256) k_build(
    const float* __restrict__ x, const float* __restrict__ z,
    const float* __restrict__ mem, const int* __restrict__ y,
    const int* __restrict__ idx, float* __restrict__ out)
{
    const unsigned t = blockIdx.x * 256u + threadIdx.x;
    if (t >= (unsigned)LOGITS) return;

    unsigned b, k; int row;
    if (t < BSZ) {                       // positives: k = 0, row = y[b]
        b = t; k = 0; row = __ldg(&y[b]);
    } else {                             // negatives
        const unsigned u = t - BSZ;
        b = u >> 16;
        k = (u & 65535u) + 1u;
        row = __ldg(&idx[u]);
    }

    const unsigned slot = atomicAdd(&g_cnt[row], 1u);
    if (slot < CAP) {
        g_ent[(size_t)row * CAP + slot] = (b << 17) | k;
    } else {
        // serial fallback (probability ~0 for this input, kept for correctness)
        const float* w = mem + (size_t)row * NDIM;
        float dx = 0.0f, dz = 0.0f;
        for (int i = 0; i < NDIM; i++) {
            const float wv = __ldg(w + i);
            dx += wv * __ldg(&x[b * NDIM + i]);
            dz += wv * __ldg(&z[b * NDIM + i]);
        }
        const float lx = expf(dx * INV_T);
        const float lz = expf(dz * INV_T);
        out[(size_t)b * KP1 + k]              = lx;
        out[OUT_LZ_OFF + (size_t)b * KP1 + k] = lz;
        atomicAdd(&g_part[t & (NPART - 1)], (double)lx);
    }
}

// ---------------------------------------------------------------------------
// Pass B: stream memory once. Warp per row: copy row to new_memory AND
// compute every logit that references this row (x/z hot in L1).
// ---------------------------------------------------------------------------
__global__ void __launch_bounds__(256) k_row(
    const float* __restrict__ x, const float* __restrict__ z,
    const float* __restrict__ mem, float* __restrict__ out)
{
    const int warp = threadIdx.x >> 5;
    const int lane = threadIdx.x & 31;
    const unsigned row = blockIdx.x * 8u + warp;      // < NDATA exactly

    __shared__ double s_part[8];

    // load row once (streaming: don't pollute L1 holding x/z) and copy it out
    const float4 w = __ldcs((const float4*)(mem + (size_t)row * NDIM) + lane);
    __stcs((float4*)(out + OUT_MEM_OFF + (size_t)row * NDIM) + lane, w);

    unsigned cnt = 0;
    if (lane == 0) cnt = g_cnt[row];
    cnt = __shfl_sync(0xffffffffu, cnt, 0);
    const unsigned n = cnt < CAP ? cnt : CAP;

    unsigned my_ent = 0;
    if (lane < (int)n) my_ent = g_ent[(size_t)row * CAP + lane];

    float lsum = 0.0f;
    for (unsigned e = 0; e < n; e++) {
        const unsigned ent = __shfl_sync(0xffffffffu, my_ent, e);
        const unsigned b = ent >> 17;
        const unsigned k = ent & 0x1FFFFu;

        const float4 xv = __ldg((const float4*)(x + b * NDIM) + lane);
        const float4 zv = __ldg((const float4*)(z + b * NDIM) + lane);
        float dx = w.x * xv.x + w.y * xv.y + w.z * xv.z + w.w * xv.w;
        float dz = w.x * zv.x + w.y * zv.y + w.z * zv.z + w.w * zv.w;
        #pragma unroll
        for (int off = 16; off; off >>= 1) {
            dx += __shfl_xor_sync(0xffffffffu, dx, off);
            dz += __shfl_xor_sync(0xffffffffu, dz, off);
        }
        if (lane == 0) {
            const float lx = expf(dx * INV_T);
            const float lz = expf(dz * INV_T);
            out[(size_t)b * KP1 + k]              = lx;
            out[OUT_LZ_OFF + (size_t)b * KP1 + k] = lz;
            lsum += lx;
        }
    }

    if (lane == 0) {
        g_cnt[row] = 0;                    // reset bucket for next replay
        s_part[warp] = (double)lsum;
    }
    __syncthreads();
    if (threadIdx.x == 0) {
        double acc = 0.0;
        #pragma unroll
        for (int i = 0; i < 8; i++) acc += s_part[i];
        if (acc != 0.0)
            atomicAdd(&g_part[blockIdx.x & (NPART - 1)], acc);
    }
}

// ---------------------------------------------------------------------------
// Epilogue: reduce partials -> z0, scale lx/lz, EMA-scatter the 16 rows,
// last block resets partials/counter for the next graph replay.
// ---------------------------------------------------------------------------
__global__ void __launch_bounds__(256) k_finish(
    const float* __restrict__ x, const float* __restrict__ mem,
    const int* __restrict__ y, float* __restrict__ out)
{
    __shared__ double s_red[NPART];

    // parallel reduce of the 256 partials (per block; data L2-hot)
    s_red[threadIdx.x] = g_part[threadIdx.x];
    __syncthreads();
    #pragma unroll
    for (int s = NPART / 2; s > 0; s >>= 1) {
        if (threadIdx.x < s) s_red[threadIdx.x] += s_red[threadIdx.x + s];
        __syncthreads();
    }
    const double z0 = s_red[0] / (double)LOGITS * (double)NDATA;
    const float  inv = (float)(1.0 / z0);

    if (blockIdx.x < 2) {
        const int warp = threadIdx.x >> 5;
        const int lane = threadIdx.x & 31;
        const int b    = blockIdx.x * 8 + warp;   // 0..15

        const int row = __ldg(&y[b]);
        const float4 m  = __ldg((const float4*)(mem + (size_t)row * NDIM) + lane);
        const float4 xv = __ldg((const float4*)(x + b * NDIM) + lane);

        float4 wv;
        wv.x = EMA_M * m.x + (1.0f - EMA_M) * xv.x;
        wv.y = EMA_M * m.y + (1.0f - EMA_M) * xv.y;
        wv.z = EMA_M * m.z + (1.0f - EMA_M) * xv.z;
        wv.w = EMA_M * m.w + (1.0f - EMA_M) * xv.w;

        float nrm = wv.x * wv.x + wv.y * wv.y + wv.z * wv.z + wv.w * wv.w;
        #pragma unroll
        for (int off = 16; off; off >>= 1)
            nrm += __shfl_xor_sync(0xffffffffu, nrm, off);
        const float rinv = rsqrtf(nrm);

        float4 o;
        o.x = wv.x * rinv; o.y = wv.y * rinv; o.z = wv.z * rinv; o.w = wv.w * rinv;
        ((float4*)(out + OUT_MEM_OFF + (size_t)row * NDIM))[lane] = o;
    }

    const size_t i = (size_t)blockIdx.x * 256 + threadIdx.x;
    if (i < N4_SCALE) {
        float4* p = (float4*)out;
        float4 v = p[i];
        v.x *= inv; v.y *= inv; v.z *= inv; v.w *= inv;
        p[i] = v;
    }

    // replay-safe reset
    __syncthreads();
    if (threadIdx.x == 0) {
        __threadfence();
        const unsigned prev = atomicAdd(&g_done, 1u);
        if (prev == FIN_BLKS - 1) {
            for (int j = 0; j < NPART; j++) g_part[j] = 0.0;
            g_done = 0u;
            __threadfence();
        }
    }
}

// ---------------------------------------------------------------------------
extern "C" void kernel_launch(void* const* d_in, const int* in_sizes, int n_in,
                              void* d_out, int out_size)
{
    const float* x   = (const float*)d_in[0];
    const float* z   = (const float*)d_in[1];
    const float* mem = (const float*)d_in[2];
    const int*   y   = (const int*)  d_in[3];
    const int*   idx = (const int*)  d_in[4];
    float*       out = (float*)d_out;

    (void)in_sizes; (void)n_in; (void)out_size;

    k_build <<<BUILD_BLKS, 256>>>(x, z, mem, y, idx, out);
    k_row   <<<ROW_BLKS,   256>>>(x, z, mem, out);
    k_finish<<<FIN_BLKS,   256>>>(x, mem, y, out);
}

// round 8
// speedup vs baseline: 1.2514x; 1.2514x over previous
#include <cuda_runtime.h>
#include <math.h>

#define BSZ    16
#define KNEG   65536
#define KP1    65537u
#define NDIM   128
#define NDATA  1000000
#define INV_T  (1.0f / 0.07f)
#define EMA_M  0.5f

#define LOGITS       (BSZ * 65537)            // 1,048,592 = 4 * 262,148
#define TOT_WARPS    (LOGITS / 4)             // 262,148
#define GBLKS        ((TOT_WARPS + 7) / 8)    // 32,769 blocks, 8 warps each

#define OUT_LZ_OFF   ((size_t)LOGITS)
#define OUT_MEM_OFF  ((size_t)2 * LOGITS)
#define N4_MEM       ((size_t)NDATA * NDIM / 4)     // 32,000,000 float4
#define N4_SCALE     ((size_t)2 * LOGITS / 4)       // 524,296 float4 (exact)
#define CP_STRIDE    ((size_t)GBLKS * 256)          // 8,388,864

#define SPIN         128u                     // blocks that stay for the epilogue
#define THRESH       ((unsigned)GBLKS - SPIN)

__device__ double       g_sum;     // exp(lx) accumulator (zero-init; reset in-kernel)
__device__ unsigned int g_done;    // block arrival counter
__device__ unsigned int g_done2;   // spinner completion counter

// ---------------------------------------------------------------------------
// Single fused kernel:
//  phase 1: every block gathers 32 logit rows (8 warps x 4 rows, 8 lanes/row)
//           + a 4-way unrolled streaming-copy slice of memory -> out
//  phase 2: block-reduce lx into g_sum, arrive on g_done
//  phase 3: the last SPIN arrivals spin until all blocks are done, then
//           scale lx/lz by 1/Z0, do the 16-row EMA scatter, reset state.
// ---------------------------------------------------------------------------
__global__ void __launch_bounds__(256) k_fused(
    const float* __restrict__ x, const float* __restrict__ z,
    const float* __restrict__ mem, const int* __restrict__ y,
    const int* __restrict__ idx, float* __restrict__ out)
{
    const int warp_in_blk = threadIdx.x >> 5;
    const int lane        = threadIdx.x & 31;
    const int grp         = lane >> 3;     // which of this warp's 4 rows
    const int li          = lane & 7;      // lane within row-group
    const unsigned warp_id = blockIdx.x * 8u + warp_in_blk;

    __shared__ double   s_part[8];
    __shared__ unsigned s_ord;             // epilogue order, ~0u = exit
    __shared__ float    s_inv;

    float lx_store = 0.0f;

    // ---------------- gather phase ----------------
    if (warp_id < (unsigned)TOT_WARPS) {
        const unsigned lg = warp_id * 4u + grp;     // logit index < LOGITS
        const unsigned b  = lg / KP1;
        const unsigned k  = lg - b * KP1;

        int row;
        if (k == 0) row = __ldg(&y[b]);
        else        row = __ldg(&idx[(size_t)b * KNEG + (k - 1)]);

        const float4* w4 = (const float4*)(mem + (size_t)row * NDIM);
        const float4* x4 = (const float4*)(x + b * NDIM);
        const float4* z4 = (const float4*)(z + b * NDIM);

        float dx = 0.0f, dz = 0.0f;
        #pragma unroll
        for (int j = 0; j < 4; j++) {
            const float4 w  = __ldg(w4 + li + 8 * j);
            const float4 xv = __ldg(x4 + li + 8 * j);
            const float4 zv = __ldg(z4 + li + 8 * j);
            dx += w.x * xv.x + w.y * xv.y + w.z * xv.z + w.w * xv.w;
            dz += w.x * zv.x + w.y * zv.y + w.z * zv.z + w.w * zv.w;
        }
        #pragma unroll
        for (int off = 4; off; off >>= 1) {
            dx += __shfl_xor_sync(0xffffffffu, dx, off);
            dz += __shfl_xor_sync(0xffffffffu, dz, off);
        }

        if (li == 0) {
            const float lx = expf(dx * INV_T);
            const float lz = expf(dz * INV_T);
            out[(size_t)b * KP1 + k]              = lx;
            out[OUT_LZ_OFF + (size_t)b * KP1 + k] = lz;
            lx_store = lx;
        }
    }

    // ---------------- streaming copy slice (4 independent iterations) ------
    {
        const size_t i0 = (size_t)blockIdx.x * 256 + threadIdx.x;  // < CP_STRIDE
        const float4* src = (const float4*)mem;
        float4*       dst = (float4*)(out + OUT_MEM_OFF);

        const float4 v0 = __ldcs(src + i0);
        const float4 v1 = __ldcs(src + i0 + CP_STRIDE);
        const float4 v2 = __ldcs(src + i0 + 2 * CP_STRIDE);
        const bool   h3 = (i0 + 3 * CP_STRIDE) < N4_MEM;
        float4 v3;
        if (h3) v3 = __ldcs(src + i0 + 3 * CP_STRIDE);

        __stcs(dst + i0,                 v0);
        __stcs(dst + i0 + CP_STRIDE,     v1);
        __stcs(dst + i0 + 2 * CP_STRIDE, v2);
        if (h3) __stcs(dst + i0 + 3 * CP_STRIDE, v3);
    }

    // ---------------- block reduction + arrival ---------------------------
    float s = lx_store;                      // nonzero only on lanes 0,8,16,24
    s += __shfl_xor_sync(0xffffffffu, s, 8);
    s += __shfl_xor_sync(0xffffffffu, s, 16);
    if (lane == 0) s_part[warp_in_blk] = (double)s;
    __syncthreads();
    if (threadIdx.x == 0) {
        double acc = 0.0;
        #pragma unroll
        for (int i = 0; i < 8; i++) acc += s_part[i];
        atomicAdd(&g_sum, acc);
        __threadfence();                     // g_sum before g_done
        const unsigned prev = atomicAdd(&g_done, 1u);
        s_ord = (prev >= THRESH) ? (prev - THRESH) : ~0u;
    }
    __syncthreads();

    const unsigned ord = s_ord;
    if (ord == ~0u) return;                  // not an epilogue block

    // ---------------- epilogue (last SPIN blocks) --------------------------
    if (threadIdx.x == 0) {
        // wait until every block has contributed g_sum and finished its copy
        while (*(volatile unsigned*)&g_done < (unsigned)GBLKS)
            __nanosleep(64);
        __threadfence();                     // acquire g_sum + all stores
        const double z0 = g_sum / (double)LOGITS * (double)NDATA;
        s_inv = (float)(1.0 / z0);
    }
    __syncthreads();
    const float inv = s_inv;

    // EMA scatter of the 16 touched rows (safe now: all copies complete)
    if (ord < 2) {
        const int b = (int)ord * 8 + warp_in_blk;   // 0..15
        const int row = __ldg(&y[b]);
        const float4 m  = __ldg((const float4*)(mem + (size_t)row * NDIM) + lane);
        const float4 xv = __ldg((const float4*)(x + b * NDIM) + lane);

        float4 wv;
        wv.x = EMA_M * m.x + (1.0f - EMA_M) * xv.x;
        wv.y = EMA_M * m.y + (1.0f - EMA_M) * xv.y;
        wv.z = EMA_M * m.z + (1.0f - EMA_M) * xv.z;
        wv.w = EMA_M * m.w + (1.0f - EMA_M) * xv.w;

        float nrm = wv.x * wv.x + wv.y * wv.y + wv.z * wv.z + wv.w * wv.w;
        #pragma unroll
        for (int off = 16; off; off >>= 1)
            nrm += __shfl_xor_sync(0xffffffffu, nrm, off);
        const float rinv = rsqrtf(nrm);

        float4 o;
        o.x = wv.x * rinv; o.y = wv.y * rinv; o.z = wv.z * rinv; o.w = wv.w * rinv;
        ((float4*)(out + OUT_MEM_OFF + (size_t)row * NDIM))[lane] = o;
    }

    // scale lx and lz by 1/Z0 (data mostly L2-resident)
    {
        float4* p = (float4*)out;
        const size_t stride = (size_t)SPIN * 256;
        for (size_t j = (size_t)ord * 256 + threadIdx.x; j < N4_SCALE; j += stride) {
            float4 v = p[j];
            v.x *= inv; v.y *= inv; v.z *= inv; v.w *= inv;
            p[j] = v;
        }
    }

    // ---------------- replay-safe reset ------------------------------------
    __syncthreads();
    if (threadIdx.x == 0) {
        __threadfence();
        const unsigned prev2 = atomicAdd(&g_done2, 1u);
        if (prev2 == SPIN - 1) {             // last epilogue block
            g_sum   = 0.0;
            g_done  = 0u;
            g_done2 = 0u;
            __threadfence();
        }
    }
}

// ---------------------------------------------------------------------------
extern "C" void kernel_launch(void* const* d_in, const int* in_sizes, int n_in,
                              void* d_out, int out_size)
{
    const float* x   = (const float*)d_in[0];
    const float* z   = (const float*)d_in[1];
    const float* mem = (const float*)d_in[2];
    const int*   y   = (const int*)  d_in[3];
    const int*   idx = (const int*)  d_in[4];
    float*       out = (float*)d_out;

    (void)in_sizes; (void)n_in; (void)out_size;

    k_fused<<<GBLKS, 256>>>(x, z, mem, y, idx, out);
}

// round 9
// speedup vs baseline: 1.3228x; 1.0570x over previous
#include <cuda_runtime.h>
#include <math.h>

#define BSZ    16
#define KNEG   65536
#define KP1    65537u
#define NDIM   128
#define NDATA  1000000
#define INV_T  (1.0f / 0.07f)
#define EMA_M  0.5f

#define LOGITS       (BSZ * 65537)            // 1,048,592 = 4 * 262,148
#define TOT_WARPS    (LOGITS / 4)             // 262,148
#define GBLKS        ((TOT_WARPS + 7) / 8)    // 32,769 blocks, 8 warps each

#define OUT_LZ_OFF   ((size_t)LOGITS)
#define OUT_MEM_OFF  ((size_t)2 * LOGITS)
#define N4_MEM       ((size_t)NDATA * NDIM / 4)     // 32,000,000 float4
#define N4_SCALE     ((size_t)2 * LOGITS / 4)       // 524,296 float4 (exact)
#define CP_STRIDE    ((size_t)GBLKS * 256)          // 8,388,864

#define FIN_BLKS     ((unsigned)((N4_SCALE + 255) / 256))   // 2049

__device__ double       g_sum;    // zero-initialized; k_finish resets it each replay
__device__ unsigned int g_done;   // arrival counter for the reset

// ---------------------------------------------------------------------------
// Every block: (1) gather+dot+exp for 32 logit rows (8 warps x 4 rows,
// 8 lanes/row), packed float4 stores of lx/lz, (2) a 4-way unrolled
// streaming-copy slice of memory -> out, (3) block-reduce lx into g_sum.
// ---------------------------------------------------------------------------
__global__ void __launch_bounds__(256) k_fused(
    const float* __restrict__ x, const float* __restrict__ z,
    const float* __restrict__ mem, const int* __restrict__ y,
    const int* __restrict__ idx, float* __restrict__ out)
{
    const int warp_in_blk = threadIdx.x >> 5;
    const int lane        = threadIdx.x & 31;
    const int grp         = lane >> 3;     // which of this warp's 4 rows
    const int li          = lane & 7;      // lane within row-group
    const unsigned warp_id = blockIdx.x * 8u + warp_in_blk;

    __shared__ double s_part[8];

    double acc = 0.0;

    // ---------------- gather phase ----------------
    if (warp_id < (unsigned)TOT_WARPS) {
        const unsigned lg = warp_id * 4u + grp;     // logit index < LOGITS
        const unsigned b  = lg / KP1;
        const unsigned k  = lg - b * KP1;

        int row;
        if (k == 0) row = __ldg(&y[b]);
        else        row = __ldg(&idx[(size_t)b * KNEG + (k - 1)]);

        const float4* w4 = (const float4*)(mem + (size_t)row * NDIM);
        const float4* x4 = (const float4*)(x + b * NDIM);
        const float4* z4 = (const float4*)(z + b * NDIM);

        float dx = 0.0f, dz = 0.0f;
        #pragma unroll
        for (int j = 0; j < 4; j++) {
            const float4 w  = __ldg(w4 + li + 8 * j);
            const float4 xv = __ldg(x4 + li + 8 * j);
            const float4 zv = __ldg(z4 + li + 8 * j);
            dx += w.x * xv.x + w.y * xv.y + w.z * xv.z + w.w * xv.w;
            dz += w.x * zv.x + w.y * zv.y + w.z * zv.z + w.w * zv.w;
        }
        #pragma unroll
        for (int off = 4; off; off >>= 1) {
            dx += __shfl_xor_sync(0xffffffffu, dx, off);
            dz += __shfl_xor_sync(0xffffffffu, dz, off);
        }

        // exp on leader lanes (0,8,16,24); other lanes hold garbage (unused)
        const float lx = expf(dx * INV_T);
        const float lz = expf(dz * INV_T);

        // collect the 4 leaders' results on lane 0, emit two STG.128
        const float l0 = __shfl_sync(0xffffffffu, lx, 0);
        const float l1 = __shfl_sync(0xffffffffu, lx, 8);
        const float l2 = __shfl_sync(0xffffffffu, lx, 16);
        const float l3 = __shfl_sync(0xffffffffu, lx, 24);
        const float m0 = __shfl_sync(0xffffffffu, lz, 0);
        const float m1 = __shfl_sync(0xffffffffu, lz, 8);
        const float m2 = __shfl_sync(0xffffffffu, lz, 16);
        const float m3 = __shfl_sync(0xffffffffu, lz, 24);

        if (lane == 0) {
            const size_t lg0 = (size_t)warp_id * 4;   // 16B-aligned out index
            float4 v;
            v.x = l0; v.y = l1; v.z = l2; v.w = l3;
            *(float4*)(out + lg0) = v;
            float4 u;
            u.x = m0; u.y = m1; u.z = m2; u.w = m3;
            *(float4*)(out + OUT_LZ_OFF + lg0) = u;
            acc = ((double)l0 + (double)l1) + ((double)l2 + (double)l3);
        }
    }

    // ---------------- streaming copy slice (4 independent iterations) ------
    {
        const size_t i0 = (size_t)blockIdx.x * 256 + threadIdx.x;  // < CP_STRIDE
        const float4* src = (const float4*)mem;
        float4*       dst = (float4*)(out + OUT_MEM_OFF);

        const float4 v0 = __ldcs(src + i0);
        const float4 v1 = __ldcs(src + i0 + CP_STRIDE);
        const float4 v2 = __ldcs(src + i0 + 2 * CP_STRIDE);
        const bool   h3 = (i0 + 3 * CP_STRIDE) < N4_MEM;
        float4 v3;
        if (h3) v3 = __ldcs(src + i0 + 3 * CP_STRIDE);

        __stcs(dst + i0,                 v0);
        __stcs(dst + i0 + CP_STRIDE,     v1);
        __stcs(dst + i0 + 2 * CP_STRIDE, v2);
        if (h3) __stcs(dst + i0 + 3 * CP_STRIDE, v3);
    }

    // ---------------- block reduction into g_sum ---------------------------
    if (lane == 0) s_part[warp_in_blk] = acc;
    __syncthreads();
    if (threadIdx.x == 0) {
        double t = 0.0;
        #pragma unroll
        for (int i = 0; i < 8; i++) t += s_part[i];
        atomicAdd(&g_sum, t);
    }

#if __CUDA_ARCH__ >= 900
    // let the dependent k_finish grid begin launching while we drain
    cudaTriggerProgrammaticLaunchCompletion();
#endif
}

// ---------------------------------------------------------------------------
// Epilogue (PDL): wait for k_fused, scale lx/lz by 1/Z0; blocks 0-1 do the
// 16-row EMA scatter; the last block resets g_sum/g_done for the next replay.
// ---------------------------------------------------------------------------
__global__ void __launch_bounds__(256) k_finish(
    const float* __restrict__ x, const float* __restrict__ mem,
    const int* __restrict__ y, float* __restrict__ out)
{
#if __CUDA_ARCH__ >= 900
    cudaGridDependencySynchronize();   // all k_fused stores now visible
#endif

    __shared__ float s_inv;
    if (threadIdx.x == 0) {
        const double z0 = g_sum / (double)LOGITS * (double)NDATA;
        s_inv = (float)(1.0 / z0);
    }
    __syncthreads();
    const float inv = s_inv;

    if (blockIdx.x < 2) {
        const int warp = threadIdx.x >> 5;
        const int lane = threadIdx.x & 31;
        const int b    = blockIdx.x * 8 + warp;   // 0..15

        const int row = __ldg(&y[b]);
        const float4 m  = __ldg((const float4*)(mem + (size_t)row * NDIM) + lane);
        const float4 xv = __ldg((const float4*)(x + b * NDIM) + lane);

        float4 w;
        w.x = EMA_M * m.x + (1.0f - EMA_M) * xv.x;
        w.y = EMA_M * m.y + (1.0f - EMA_M) * xv.y;
        w.z = EMA_M * m.z + (1.0f - EMA_M) * xv.z;
        w.w = EMA_M * m.w + (1.0f - EMA_M) * xv.w;

        float nrm = w.x * w.x + w.y * w.y + w.z * w.z + w.w * w.w;
        #pragma unroll
        for (int off = 16; off; off >>= 1)
            nrm += __shfl_xor_sync(0xffffffffu, nrm, off);
        const float rinv = rsqrtf(nrm);

        float4 o;
        o.x = w.x * rinv; o.y = w.y * rinv; o.z = w.z * rinv; o.w = w.w * rinv;
        ((float4*)(out + OUT_MEM_OFF + (size_t)row * NDIM))[lane] = o;
    }

    const size_t i = (size_t)blockIdx.x * 256 + threadIdx.x;
    if (i < N4_SCALE) {
        float4* p = (float4*)out;
        float4 v = p[i];
        v.x *= inv; v.y *= inv; v.z *= inv; v.w *= inv;
        p[i] = v;
    }

    // ----- replay-safe reset of the accumulator ----------------------------
    __syncthreads();
    if (threadIdx.x == 0) {
        __threadfence();                      // order g_sum read before arrival
        const unsigned prev = atomicAdd(&g_done, 1u);
        if (prev == FIN_BLKS - 1) {           // last block of this replay
            g_sum  = 0.0;
            g_done = 0u;
            __threadfence();
        }
    }
}

// ---------------------------------------------------------------------------
extern "C" void kernel_launch(void* const* d_in, const int* in_sizes, int n_in,
                              void* d_out, int out_size)
{
    const float* x   = (const float*)d_in[0];
    const float* z   = (const float*)d_in[1];
    const float* mem = (const float*)d_in[2];
    const int*   y   = (const int*)  d_in[3];
    const int*   idx = (const int*)  d_in[4];
    float*       out = (float*)d_out;

    (void)in_sizes; (void)n_in; (void)out_size;

    k_fused<<<GBLKS, 256>>>(x, z, mem, y, idx, out);

    // k_finish via PDL: launch overlaps k_fused's drain; the in-kernel
    // cudaGridDependencySynchronize provides the ordering guarantee.
    cudaLaunchConfig_t cfg = {};
    cfg.gridDim  = dim3(FIN_BLKS, 1, 1);
    cfg.blockDim = dim3(256, 1, 1);
    cudaLaunchAttribute attr[1];
    attr[0].id = cudaLaunchAttributeProgrammaticStreamSerialization;
    attr[0].val.programmaticStreamSerializationAllowed = 1;
    cfg.attrs    = attr;
    cfg.numAttrs = 1;
    cudaLaunchKernelEx(&cfg, k_finish, x, mem, y, out);
}

// round 10
// speedup vs baseline: 1.3732x; 1.0382x over previous
#include <cuda_runtime.h>
#include <math.h>

#define BSZ    16
#define KNEG   65536
#define KP1    65537u
#define NDIM   128
#define NDATA  1000000
#define INV_T  (1.0f / 0.07f)
#define EMA_M  0.5f

#define LOGITS       (BSZ * 65537)            // 1,048,592 = 4 * 262,148
#define TOT_WARPS    (LOGITS / 4)             // 262,148
#define GBLKS        ((TOT_WARPS + 7) / 8)    // 32,769 blocks, 8 warps each

#define OUT_LZ_OFF   ((size_t)LOGITS)
#define OUT_MEM_OFF  ((size_t)2 * LOGITS)
#define N4_MEM       ((size_t)NDATA * NDIM / 4)     // 32,000,000 float4
#define N4_SCALE     ((size_t)2 * LOGITS / 4)       // 524,296 float4 (exact)
#define CP_STRIDE    ((size_t)GBLKS * 256)          // 8,388,864

#define FIN_BLKS     592u                           // 4 ILP iters per thread
#define FIN_STRIDE   ((size_t)FIN_BLKS * 256)       // 151,552

__device__ double       g_sum;    // zero-initialized; k_finish resets it each replay
__device__ unsigned int g_done;   // arrival counter for the reset

// ---------------------------------------------------------------------------
// Every block: (1) gather+dot+exp for 32 logit rows (8 warps x 4 rows,
// 8 lanes/row), (2) a 4-way unrolled streaming-copy slice of memory -> out,
// (3) block-reduce lx into g_sum.   [byte-identical to the R3 version]
// ---------------------------------------------------------------------------
__global__ void __launch_bounds__(256) k_fused(
    const float* __restrict__ x, const float* __restrict__ z,
    const float* __restrict__ mem, const int* __restrict__ y,
    const int* __restrict__ idx, float* __restrict__ out)
{
    const int warp_in_blk = threadIdx.x >> 5;
    const int lane        = threadIdx.x & 31;
    const int grp         = lane >> 3;     // which of this warp's 4 rows
    const int li          = lane & 7;      // lane within row-group
    const unsigned warp_id = blockIdx.x * 8u + warp_in_blk;

    __shared__ double s_part[8];

    float lx_store = 0.0f;

    // ---------------- gather phase ----------------
    if (warp_id < (unsigned)TOT_WARPS) {
        const unsigned lg = warp_id * 4u + grp;     // logit index < LOGITS
        const unsigned b  = lg / KP1;
        const unsigned k  = lg - b * KP1;

        int row;
        if (k == 0) row = __ldg(&y[b]);
        else        row = __ldg(&idx[(size_t)b * KNEG + (k - 1)]);

        const float4* w4 = (const float4*)(mem + (size_t)row * NDIM);
        const float4* x4 = (const float4*)(x + b * NDIM);
        const float4* z4 = (const float4*)(z + b * NDIM);

        float dx = 0.0f, dz = 0.0f;
        #pragma unroll
        for (int j = 0; j < 4; j++) {
            const float4 w  = __ldg(w4 + li + 8 * j);
            const float4 xv = __ldg(x4 + li + 8 * j);
            const float4 zv = __ldg(z4 + li + 8 * j);
            dx += w.x * xv.x + w.y * xv.y + w.z * xv.z + w.w * xv.w;
            dz += w.x * zv.x + w.y * zv.y + w.z * zv.z + w.w * zv.w;
        }
        #pragma unroll
        for (int off = 4; off; off >>= 1) {
            dx += __shfl_xor_sync(0xffffffffu, dx, off);
            dz += __shfl_xor_sync(0xffffffffu, dz, off);
        }

        if (li == 0) {
            const float lx = expf(dx * INV_T);
            const float lz = expf(dz * INV_T);
            out[(size_t)b * KP1 + k]              = lx;
            out[OUT_LZ_OFF + (size_t)b * KP1 + k] = lz;
            lx_store = lx;
        }
    }

    // ---------------- streaming copy slice (4 independent iterations) ------
    {
        const size_t i0 = (size_t)blockIdx.x * 256 + threadIdx.x;  // < CP_STRIDE
        const float4* src = (const float4*)mem;
        float4*       dst = (float4*)(out + OUT_MEM_OFF);

        const float4 v0 = __ldcs(src + i0);
        const float4 v1 = __ldcs(src + i0 + CP_STRIDE);
        const float4 v2 = __ldcs(src + i0 + 2 * CP_STRIDE);
        const bool   h3 = (i0 + 3 * CP_STRIDE) < N4_MEM;
        float4 v3;
        if (h3) v3 = __ldcs(src + i0 + 3 * CP_STRIDE);

        __stcs(dst + i0,                 v0);
        __stcs(dst + i0 + CP_STRIDE,     v1);
        __stcs(dst + i0 + 2 * CP_STRIDE, v2);
        if (h3) __stcs(dst + i0 + 3 * CP_STRIDE, v3);
    }

    // ---------------- block reduction into g_sum ---------------------------
    float s = lx_store;                      // nonzero only on lanes 0,8,16,24
    s += __shfl_xor_sync(0xffffffffu, s, 8);
    s += __shfl_xor_sync(0xffffffffu, s, 16);
    if (lane == 0) s_part[warp_in_blk] = (double)s;
    __syncthreads();
    if (threadIdx.x == 0) {
        double acc = 0.0;
        #pragma unroll
        for (int i = 0; i < 8; i++) acc += s_part[i];
        atomicAdd(&g_sum, acc);
    }
}

// ---------------------------------------------------------------------------
// Epilogue: scale lx/lz by 1/Z0 with 4-way ILP over L2-resident data;
// blocks 0-1 also do the 16-row EMA scatter; last block resets for replay.
// ---------------------------------------------------------------------------
__global__ void __launch_bounds__(256) k_finish(
    const float* __restrict__ x, const float* __restrict__ mem,
    const int* __restrict__ y, float* __restrict__ out)
{
    __shared__ float s_inv;
    if (threadIdx.x == 0) {
        const double z0 = g_sum / (double)LOGITS * (double)NDATA;
        s_inv = (float)(1.0 / z0);
    }
    __syncthreads();
    const float inv = s_inv;

    if (blockIdx.x < 2) {
        const int warp = threadIdx.x >> 5;
        const int lane = threadIdx.x & 31;
        const int b    = blockIdx.x * 8 + warp;   // 0..15

        const int row = __ldg(&y[b]);
        const float4 m  = __ldg((const float4*)(mem + (size_t)row * NDIM) + lane);
        const float4 xv = __ldg((const float4*)(x + b * NDIM) + lane);

        float4 w;
        w.x = EMA_M * m.x + (1.0f - EMA_M) * xv.x;
        w.y = EMA_M * m.y + (1.0f - EMA_M) * xv.y;
        w.z = EMA_M * m.z + (1.0f - EMA_M) * xv.z;
        w.w = EMA_M * m.w + (1.0f - EMA_M) * xv.w;

        float nrm = w.x * w.x + w.y * w.y + w.z * w.z + w.w * w.w;
        #pragma unroll
        for (int off = 16; off; off >>= 1)
            nrm += __shfl_xor_sync(0xffffffffu, nrm, off);
        const float rinv = rsqrtf(nrm);

        float4 o;
        o.x = w.x * rinv; o.y = w.y * rinv; o.z = w.z * rinv; o.w = w.w * rinv;
        ((float4*)(out + OUT_MEM_OFF + (size_t)row * NDIM))[lane] = o;
    }

    // 4 independent strided load/scale/store pairs per thread (MLP=4)
    {
        float4* p = (float4*)out;
        const size_t i0 = (size_t)blockIdx.x * 256 + threadIdx.x;  // < FIN_STRIDE

        const size_t j0 = i0;                          // < 151,552      ok
        const size_t j1 = i0 + FIN_STRIDE;             // < 303,104      ok
        const size_t j2 = i0 + 2 * FIN_STRIDE;         // < 454,656      ok
        const size_t j3 = i0 + 3 * FIN_STRIDE;         // may exceed N4_SCALE
        const bool   h3 = j3 < N4_SCALE;

        float4 v0 = p[j0];
        float4 v1 = p[j1];
        float4 v2 = p[j2];
        float4 v3;
        if (h3) v3 = p[j3];

        v0.x *= inv; v0.y *= inv; v0.z *= inv; v0.w *= inv;
        v1.x *= inv; v1.y *= inv; v1.z *= inv; v1.w *= inv;
        v2.x *= inv; v2.y *= inv; v2.z *= inv; v2.w *= inv;
        p[j0] = v0;
        p[j1] = v1;
        p[j2] = v2;
        if (h3) {
            v3.x *= inv; v3.y *= inv; v3.z *= inv; v3.w *= inv;
            p[j3] = v3;
        }
    }

    // ----- replay-safe reset of the accumulator ----------------------------
    __syncthreads();
    if (threadIdx.x == 0) {
        __threadfence();                      // order g_sum read before arrival
        const unsigned prev = atomicAdd(&g_done, 1u);
        if (prev == FIN_BLKS - 1) {           // last block of this replay
            g_sum  = 0.0;
            g_done = 0u;
            __threadfence();
        }
    }
}

// ---------------------------------------------------------------------------
extern "C" void kernel_launch(void* const* d_in, const int* in_sizes, int n_in,
                              void* d_out, int out_size)
{
    const float* x   = (const float*)d_in[0];
    const float* z   = (const float*)d_in[1];
    const float* mem = (const float*)d_in[2];
    const int*   y   = (const int*)  d_in[3];
    const int*   idx = (const int*)  d_in[4];
    float*       out = (float*)d_out;

    (void)in_sizes; (void)n_in; (void)out_size;

    k_fused <<<GBLKS,    256>>>(x, z, mem, y, idx, out);
    k_finish<<<FIN_BLKS, 256>>>(x, mem, y, out);
}

// round 11
// speedup vs baseline: 1.4077x; 1.0251x over previous
#include <cuda_runtime.h>
#include <math.h>

#define BSZ    16
#define KNEG   65536
#define KP1    65537u
#define NDIM   128
#define NDATA  1000000
#define INV_T  (1.0f / 0.07f)
#define EMA_M  0.5f

#define LOGITS       (BSZ * 65537)            // 1,048,592
#define NPHASE       16
#define RPP          (NDATA / NPHASE)         // 62,500 rows per phase window
#define PW4          ((size_t)RPP * NDIM / 4) // 2,000,000 float4 per window
#define BPP          2176                     // blocks per phase
#define TOTBLK       (NPHASE * BPP)           // 34,816
#define CAPB         131072                   // bin capacity (entries)

#define OUT_LZ_OFF   ((size_t)LOGITS)
#define OUT_MEM_OFF  ((size_t)2 * LOGITS)
#define N4_MEM       ((size_t)NDATA * NDIM / 4)     // 32,000,000
#define N4_SCALE     ((size_t)2 * LOGITS / 4)       // 524,296 (exact)

#define BIN_BLKS     ((LOGITS + 255) / 256)         // 4097
#define FIN_BLKS     592u
#define FIN_STRIDE   ((size_t)FIN_BLKS * 256)

__device__ double   g_sum;              // zero-init; reset by k_finish each replay
__device__ unsigned g_done;
__device__ unsigned g_bcnt[NPHASE];     // per-phase entry counts
__device__ uint2    g_ent[(size_t)NPHASE * CAPB];   // 16 MB entry store

// ---------------------------------------------------------------------------
// Pass 1: bin every logit by memory-row phase.  Block-aggregated smem prefix
// -> 16 global atomics per block.  Entry = { (b<<20)|row , k }.
// ---------------------------------------------------------------------------
__global__ void __launch_bounds__(256) k_bin(
    const float* __restrict__ x, const float* __restrict__ z,
    const float* __restrict__ mem, const int* __restrict__ y,
    const int* __restrict__ idx, float* __restrict__ out)
{
    __shared__ unsigned s_cnt[NPHASE];
    __shared__ unsigned s_base[NPHASE];
    if (threadIdx.x < NPHASE) s_cnt[threadIdx.x] = 0;
    __syncthreads();

    const unsigned t = blockIdx.x * 256u + threadIdx.x;
    const bool valid = t < (unsigned)LOGITS;

    unsigned b = 0, k = 0, bin = 0, lslot = 0;
    int row = 0;
    if (valid) {
        if (t < BSZ) { b = t; k = 0; row = __ldg(&y[b]); }
        else {
            const unsigned u = t - BSZ;
            b = u >> 16;
            k = (u & 65535u) + 1u;
            row = __ldg(&idx[u]);
        }
        bin   = (unsigned)row / RPP;
        lslot = atomicAdd(&s_cnt[bin], 1u);
    }
    __syncthreads();
    if (threadIdx.x < NPHASE && s_cnt[threadIdx.x])
        s_base[threadIdx.x] = atomicAdd(&g_bcnt[threadIdx.x], s_cnt[threadIdx.x]);
    __syncthreads();

    if (valid) {
        const unsigned slot = s_base[bin] + lslot;
        if (slot < CAPB) {
            g_ent[(size_t)bin * CAPB + slot] = make_uint2((b << 20) | (unsigned)row, k);
        } else {
            // capacity overflow fallback (never for this input): compute inline
            const float* w = mem + (size_t)row * NDIM;
            float dx = 0.0f, dz = 0.0f;
            for (int i = 0; i < NDIM; i++) {
                const float wv = __ldg(w + i);
                dx += wv * __ldg(&x[b * NDIM + i]);
                dz += wv * __ldg(&z[b * NDIM + i]);
            }
            const float lx = expf(dx * INV_T);
            const float lz = expf(dz * INV_T);
            out[(size_t)b * KP1 + k]              = lx;
            out[OUT_LZ_OFF + (size_t)b * KP1 + k] = lz;
            atomicAdd(&g_sum, (double)lx);
        }
    }
}

// ---------------------------------------------------------------------------
// Pass 2: phase p blocks stream-copy window p (cached loads keep the window
// in L2) and process bin p's gather entries (row reads -> L2 hits).
// Last block of each phase loops to absorb any count beyond the slot budget.
// ---------------------------------------------------------------------------
__global__ void __launch_bounds__(256) k_main(
    const float* __restrict__ x, const float* __restrict__ z,
    const float* __restrict__ mem, float* __restrict__ out)
{
    const unsigned phase = blockIdx.x / BPP;
    const unsigned lblk  = blockIdx.x - phase * BPP;
    const int warp = threadIdx.x >> 5;
    const int lane = threadIdx.x & 31;
    const int grp  = lane >> 3;
    const int li   = lane & 7;

    __shared__ double s_part[8];

    // ---- copy this phase's window slice (default-cached loads) ----
    {
        const size_t wbeg = (size_t)phase * PW4;
        const size_t wend = wbeg + PW4;
        const float4* src = (const float4*)mem;
        float4*       dst = (float4*)(out + OUT_MEM_OFF);
        for (size_t i = wbeg + (size_t)lblk * 256 + threadIdx.x; i < wend;
             i += (size_t)BPP * 256)
            __stcs(dst + i, __ldg(src + i));
    }

    // ---- gather entries of this phase's bin ----
    const unsigned count = min(g_bcnt[phase], (unsigned)CAPB);
    const size_t bin_base = (size_t)phase * CAPB;

    float lsum = 0.0f;
    unsigned base = lblk * 32u;
    do {
        const unsigned e  = base + (unsigned)(warp * 4 + grp);
        const bool     ok = e < count;
        const unsigned ee = ok ? e : 0u;      // stale slots hold valid packings

        const uint2 ent   = __ldg(&g_ent[bin_base + ee]);
        const unsigned row = ent.x & 0xFFFFFu;
        const unsigned b   = ent.x >> 20;
        const unsigned k   = ent.y;

        const float4* w4 = (const float4*)(mem + (size_t)row * NDIM);
        const float4* x4 = (const float4*)(x + b * NDIM);
        const float4* z4 = (const float4*)(z + b * NDIM);

        float dx = 0.0f, dz = 0.0f;
        #pragma unroll
        for (int j = 0; j < 4; j++) {
            const float4 w  = __ldg(w4 + li + 8 * j);
            const float4 xv = __ldg(x4 + li + 8 * j);
            const float4 zv = __ldg(z4 + li + 8 * j);
            dx += w.x * xv.x + w.y * xv.y + w.z * xv.z + w.w * xv.w;
            dz += w.x * zv.x + w.y * zv.y + w.z * zv.z + w.w * zv.w;
        }
        #pragma unroll
        for (int off = 4; off; off >>= 1) {
            dx += __shfl_xor_sync(0xffffffffu, dx, off);
            dz += __shfl_xor_sync(0xffffffffu, dz, off);
        }

        if (li == 0 && ok) {
            const float lx = expf(dx * INV_T);
            const float lz = expf(dz * INV_T);
            out[(size_t)b * KP1 + k]              = lx;
            out[OUT_LZ_OFF + (size_t)b * KP1 + k] = lz;
            lsum += lx;
        }
        base += 32u;
    } while (lblk == BPP - 1 && base < count);   // tail absorber (uniform)

    // ---- block reduction into g_sum ----
    float s = lsum;                          // nonzero only on lanes 0,8,16,24
    s += __shfl_xor_sync(0xffffffffu, s, 8);
    s += __shfl_xor_sync(0xffffffffu, s, 16);
    if (lane == 0) s_part[warp] = (double)s;
    __syncthreads();
    if (threadIdx.x == 0) {
        double acc = 0.0;
        #pragma unroll
        for (int i = 0; i < 8; i++) acc += s_part[i];
        atomicAdd(&g_sum, acc);
    }
}

// ---------------------------------------------------------------------------
// Pass 3: scale lx/lz by 1/Z0 (MLP=4), 16-row EMA scatter, replay reset.
// ---------------------------------------------------------------------------
__global__ void __launch_bounds__(256) k_finish(
    const float* __restrict__ x, const float* __restrict__ mem,
    const int* __restrict__ y, float* __restrict__ out)
{
    __shared__ float s_inv;
    if (threadIdx.x == 0) {
        const double z0 = g_sum / (double)LOGITS * (double)NDATA;
        s_inv = (float)(1.0 / z0);
    }
    __syncthreads();
    const float inv = s_inv;

    if (blockIdx.x < 2) {
        const int warp = threadIdx.x >> 5;
        const int lane = threadIdx.x & 31;
        const int b    = blockIdx.x * 8 + warp;   // 0..15

        const int row = __ldg(&y[b]);
        const float4 m  = __ldg((const float4*)(mem + (size_t)row * NDIM) + lane);
        const float4 xv = __ldg((const float4*)(x + b * NDIM) + lane);

        float4 w;
        w.x = EMA_M * m.x + (1.0f - EMA_M) * xv.x;
        w.y = EMA_M * m.y + (1.0f - EMA_M) * xv.y;
        w.z = EMA_M * m.z + (1.0f - EMA_M) * xv.z;
        w.w = EMA_M * m.w + (1.0f - EMA_M) * xv.w;

        float nrm = w.x * w.x + w.y * w.y + w.z * w.z + w.w * w.w;
        #pragma unroll
        for (int off = 16; off; off >>= 1)
            nrm += __shfl_xor_sync(0xffffffffu, nrm, off);
        const float rinv = rsqrtf(nrm);

        float4 o;
        o.x = w.x * rinv; o.y = w.y * rinv; o.z = w.z * rinv; o.w = w.w * rinv;
        ((float4*)(out + OUT_MEM_OFF + (size_t)row * NDIM))[lane] = o;
    }

    {
        float4* p = (float4*)out;
        const size_t i0 = (size_t)blockIdx.x * 256 + threadIdx.x;
        const size_t j0 = i0;
        const size_t j1 = i0 + FIN_STRIDE;
        const size_t j2 = i0 + 2 * FIN_STRIDE;
        const size_t j3 = i0 + 3 * FIN_STRIDE;
        const bool   h3 = j3 < N4_SCALE;

        float4 v0 = p[j0];
        float4 v1 = p[j1];
        float4 v2 = p[j2];
        float4 v3;
        if (h3) v3 = p[j3];

        v0.x *= inv; v0.y *= inv; v0.z *= inv; v0.w *= inv;
        v1.x *= inv; v1.y *= inv; v1.z *= inv; v1.w *= inv;
        v2.x *= inv; v2.y *= inv; v2.z *= inv; v2.w *= inv;
        p[j0] = v0;
        p[j1] = v1;
        p[j2] = v2;
        if (h3) {
            v3.x *= inv; v3.y *= inv; v3.z *= inv; v3.w *= inv;
            p[j3] = v3;
        }
    }

    // replay-safe reset
    __syncthreads();
    if (threadIdx.x == 0) {
        __threadfence();
        const unsigned prev = atomicAdd(&g_done, 1u);
        if (prev == FIN_BLKS - 1) {
            g_sum  = 0.0;
            g_done = 0u;
            #pragma unroll
            for (int i = 0; i < NPHASE; i++) g_bcnt[i] = 0u;
            __threadfence();
        }
    }
}

// ---------------------------------------------------------------------------
extern "C" void kernel_launch(void* const* d_in, const int* in_sizes, int n_in,
                              void* d_out, int out_size)
{
    const float* x   = (const float*)d_in[0];
    const float* z   = (const float*)d_in[1];
    const float* mem = (const float*)d_in[2];
    const int*   y   = (const int*)  d_in[3];
    const int*   idx = (const int*)  d_in[4];
    float*       out = (float*)d_out;

    (void)in_sizes; (void)n_in; (void)out_size;

    k_bin   <<<BIN_BLKS, 256>>>(x, z, mem, y, idx, out);
    k_main  <<<TOTBLK,   256>>>(x, z, mem, out);
    k_finish<<<FIN_BLKS, 256>>>(x, mem, y, out);
}